// round 11
// baseline (speedup 1.0000x reference)
#include <cuda_runtime.h>
#include <cuda_fp16.h>
#include <cstdint>
#include <math.h>

#define BATCH  2
#define SEQ    2048
#define DMODEL 2048
#define NHEAD  16
#define NKV    4
#define HDIM   128
#define KVDIM  1024
#define QKVW   3072            // fused q|k|v row width
#define MTOT   4096

#define SCALE_LOG2E 0.12751589542466683f   // (1/sqrt(128)) * log2(e)

// ---------------- scratch ----------------
__device__ __half g_xh  [(size_t)MTOT * DMODEL];
__device__ __half g_wh  [(size_t)QKVW * DMODEL];     // [Wq; Wkv] fp16
__device__ __half g_wph [(size_t)DMODEL * DMODEL];
__device__ __half g_qkvh[(size_t)MTOT * QKVW];       // fused q|k|v fp16
__device__ __half g_yh  [(size_t)MTOT * DMODEL];

// ---------------- helpers ----------------
__device__ __forceinline__ uint32_t smem_u32(const void* p) {
    uint32_t a;
    asm("{ .reg .u64 t; cvta.to.shared.u64 t, %1; cvt.u32.u64 %0, t; }" : "=r"(a) : "l"(p));
    return a;
}
__device__ __forceinline__ void ldsm_x4(uint32_t* r, uint32_t addr) {
    asm volatile("ldmatrix.sync.aligned.m8n8.x4.shared.b16 {%0,%1,%2,%3}, [%4];"
                 : "=r"(r[0]), "=r"(r[1]), "=r"(r[2]), "=r"(r[3]) : "r"(addr));
}
__device__ __forceinline__ void ldsm_x4_t(uint32_t* r, uint32_t addr) {
    asm volatile("ldmatrix.sync.aligned.m8n8.x4.trans.shared.b16 {%0,%1,%2,%3}, [%4];"
                 : "=r"(r[0]), "=r"(r[1]), "=r"(r[2]), "=r"(r[3]) : "r"(addr));
}
__device__ __forceinline__ void mma_f16(float* d, const uint32_t* a, const uint32_t* b) {
    asm volatile(
        "mma.sync.aligned.m16n8k16.row.col.f32.f16.f16.f32 "
        "{%0,%1,%2,%3}, {%4,%5,%6,%7}, {%8,%9}, {%0,%1,%2,%3};"
        : "+f"(d[0]), "+f"(d[1]), "+f"(d[2]), "+f"(d[3])
        : "r"(a[0]), "r"(a[1]), "r"(a[2]), "r"(a[3]), "r"(b[0]), "r"(b[1]));
}
__device__ __forceinline__ uint32_t h2_as_u32(__half2 v) {
    return *reinterpret_cast<uint32_t*>(&v);
}
__device__ __forceinline__ void cp_async16(uint32_t dst, const void* src) {
    asm volatile("cp.async.cg.shared.global [%0], [%1], 16;" :: "r"(dst), "l"(src));
}
__device__ __forceinline__ void cp_commit() {
    asm volatile("cp.async.commit_group;" ::: "memory");
}
template <int N>
__device__ __forceinline__ void cp_wait() {
    asm volatile("cp.async.wait_group %0;" :: "n"(N) : "memory");
}

// ---------------- single fused fp32 -> fp16 conversion pass (MLP=4) --------
#define CVT_N1 (MTOT * DMODEL / 4)          // x
#define CVT_N2 (DMODEL * DMODEL / 4)        // Wq
#define CVT_N3 (KVDIM * DMODEL / 4)         // Wkv
#define CVT_N4 (DMODEL * DMODEL / 4)        // Wproj
#define CVT_TOTAL (CVT_N1 + CVT_N2 + CVT_N3 + CVT_N4)

__global__ void cvt_all(const float* __restrict__ x,   const float* __restrict__ wq,
                        const float* __restrict__ wkv, const float* __restrict__ wp,
                        __half* __restrict__ xh, __half* __restrict__ wh,
                        __half* __restrict__ wph)
{
    int stride = gridDim.x * blockDim.x;
    int i0 = blockIdx.x * blockDim.x + threadIdx.x;
    #pragma unroll
    for (int u = 0; u < 4; u++) {
        int i = i0 + u * stride;
        if (i >= CVT_TOTAL) return;
        const float* src;
        __half* dst;
        int j;
        if (i < CVT_N1)                        { src = x;   dst = xh;  j = i; }
        else if (i < CVT_N1 + CVT_N2)          { src = wq;  dst = wh;  j = i - CVT_N1; }
        else if (i < CVT_N1 + CVT_N2 + CVT_N3) { src = wkv; dst = wh + (size_t)DMODEL * DMODEL;
                                                 j = i - CVT_N1 - CVT_N2; }
        else                                   { src = wp;  dst = wph; j = i - CVT_N1 - CVT_N2 - CVT_N3; }
        float4 v = ((const float4*)src)[j];
        union { __half b[4]; uint2 u2; } H;
        H.b[0] = __float2half_rn(v.x); H.b[1] = __float2half_rn(v.y);
        H.b[2] = __float2half_rn(v.z); H.b[3] = __float2half_rn(v.w);
        ((uint2*)dst)[j] = H.u2;
    }
}

// ---------------- in-place fp16 RoPE; k heads (>=NHEAD) get scale folded ----
#define LOG2_10000_OVER64 0.20762050593046938f   // log2(10000)/64

__global__ void rope16(__half* __restrict__ buf, int rowstride, int nheads)
{
    int idx = blockIdx.x * blockDim.x + threadIdx.x;
    int total = MTOT * nheads * (HDIM / 2);
    if (idx >= total) return;
    int j = idx & 63;
    int h = (idx >> 6) % nheads;
    int m = idx / (64 * nheads);
    int t = m & (SEQ - 1);
    float inv_freq = exp2f(-(float)j * LOG2_10000_OVER64);
    float ang = (float)t * inv_freq;
    float s, c;
    sincosf(ang, &s, &c);
    float post = (h >= NHEAD) ? SCALE_LOG2E : 1.0f;
    size_t o = (size_t)m * rowstride + h * HDIM;
    float x1 = __half2float(buf[o + j]);
    float x2 = __half2float(buf[o + j + 64]);
    buf[o + j]      = __float2half_rn((x1 * c - x2 * s) * post);
    buf[o + j + 64] = __float2half_rn((x2 * c + x1 * s) * post);
}

// ---------------------------------------------------------------------------
// HMMA fp16 NT GEMM: C = A B^T. fp32 accum; output fp16 or fp32 (template).
// CTA 128(M)x256(N), BK=64, 8 warps (2m x 4n), warp tile 64x64.
// 1 CTA/SM, ~255 regs/thread, 3-stage cp.async.
// smem/stage = (128+256)*144 = 55296 B; 3 stages = 165888 B.
// ---------------------------------------------------------------------------
#define GBK     64
#define G_ROWB  144
#define G_ATILE (128 * G_ROWB)     // 18432
#define G_BTILE (256 * G_ROWB)     // 36864
#define G_STGB  (G_ATILE + G_BTILE)// 55296
#define G_SMEM  (3 * G_STGB)       // 165888

template <bool HALF_OUT>
__global__ __launch_bounds__(256, 1)
void gemm_mma(const __half* __restrict__ A, const __half* __restrict__ B,
              void* __restrict__ Cv, int M, int N, int K)
{
    extern __shared__ char smem[];
    const uint32_t sb0 = smem_u32(smem);
    const int tid = threadIdx.x, l = tid & 31, wid = tid >> 5;
    const int wm = wid & 1, wn = wid >> 1;          // 2m x 4n
    const int mbase = blockIdx.y * 128, nbase = blockIdx.x * 256;

    const int g_row = tid >> 3;          // 0..31
    const int g_c   = tid & 7;           // 16B chunk within 128B row

    const uint32_t laA = (uint32_t)((l & 15) * G_ROWB + (l >> 4) * 16);
    const uint32_t laB = (uint32_t)(((((l >> 4) << 3) | (l & 7)) * G_ROWB) + (((l >> 3) & 1) * 16));

    float acc[4][8][4] = {};

    auto issue = [&](int kb, int stg) {
        const uint32_t sb = sb0 + (uint32_t)stg * G_STGB;
        #pragma unroll
        for (int j = 0; j < 4; j++) {            // A: 128 rows
            int row = g_row + j * 32;
            uint32_t dst = (uint32_t)(row * G_ROWB + g_c * 16);
            cp_async16(sb + dst, A + (size_t)(mbase + row) * K + kb + g_c * 8);
        }
        #pragma unroll
        for (int j = 0; j < 8; j++) {            // B: 256 rows
            int row = g_row + j * 32;
            uint32_t dst = (uint32_t)(row * G_ROWB + g_c * 16);
            cp_async16(sb + G_ATILE + dst, B + (size_t)(nbase + row) * K + kb + g_c * 8);
        }
    };

    const int NC = K / GBK;
    issue(0, 0); cp_commit();
    issue(GBK, 1); cp_commit();

    int stg = 0;
    for (int i = 0; i < NC; i++) {
        cp_wait<1>();
        __syncthreads();
        {
            int s2 = stg + 2; if (s2 >= 3) s2 -= 3;
            if (i + 2 < NC) issue((i + 2) * GBK, s2);
            cp_commit();
        }

        const uint32_t base = sb0 + (uint32_t)stg * G_STGB;
        const uint32_t sA = base, sB = base + G_ATILE;
        #pragma unroll
        for (int ks = 0; ks < 4; ks++) {
            const uint32_t koff = ks * 32;
            uint32_t af[4][4];
            #pragma unroll
            for (int mi = 0; mi < 4; mi++) {
                uint32_t ra = (uint32_t)((wm * 64 + mi * 16) * G_ROWB) + koff + laA;
                ldsm_x4(af[mi], sA + ra);
            }
            uint32_t bf[4][4];
            #pragma unroll
            for (int nj2 = 0; nj2 < 4; nj2++) {
                uint32_t rb = (uint32_t)(((wn * 64) + nj2 * 16) * G_ROWB) + koff + laB;
                ldsm_x4(bf[nj2], sB + rb);
            }
            #pragma unroll
            for (int mi = 0; mi < 4; mi++)
                #pragma unroll
                for (int nj2 = 0; nj2 < 4; nj2++) {
                    mma_f16(acc[mi][2 * nj2],     af[mi], bf[nj2]);
                    mma_f16(acc[mi][2 * nj2 + 1], af[mi], bf[nj2] + 2);
                }
        }
        if (++stg == 3) stg = 0;
    }

    #pragma unroll
    for (int mi = 0; mi < 4; mi++) {
        int row = mbase + wm * 64 + mi * 16 + (l >> 2);
        #pragma unroll
        for (int nj = 0; nj < 8; nj++) {
            int col = nbase + wn * 64 + nj * 8 + (l & 3) * 2;
            if (HALF_OUT) {
                __half* C = (__half*)Cv;
                *(__half2*)&C[(size_t)row * N + col] =
                    __floats2half2_rn(acc[mi][nj][0], acc[mi][nj][1]);
                *(__half2*)&C[(size_t)(row + 8) * N + col] =
                    __floats2half2_rn(acc[mi][nj][2], acc[mi][nj][3]);
            } else {
                float* C = (float*)Cv;
                *(float2*)&C[(size_t)row * N + col] =
                    make_float2(acc[mi][nj][0], acc[mi][nj][1]);
                *(float2*)&C[(size_t)(row + 8) * N + col] =
                    make_float2(acc[mi][nj][2], acc[mi][nj][3]);
            }
        }
    }
}

// ---------------------------------------------------------------------------
// HMMA fp16 flash attention, causal, GQA; fused QKV input (row stride 3072).
// K pre-scaled by scale*log2e -> S already in log2 domain.
// Grid (8, 32): each CTA does qtile pair (i, 15-i): balanced single wave.
// ---------------------------------------------------------------------------
#define AQROWB  272
#define AQTILEB (128 * AQROWB)       // 34816
#define AKTILEB (64 * AQROWB)        // 17408
#define A_SQ    0
#define A_KV    (A_SQ + AQTILEB)
#define A_KVSTG (2 * AKTILEB)
#define A_SMEM  (A_KV + 2 * A_KVSTG) // 104448

__global__ __launch_bounds__(256, 2)
void attn_mma(const __half* __restrict__ QKV, __half* __restrict__ Yh)
{
    extern __shared__ char smem[];
    const uint32_t sb = smem_u32(smem);
    const int tid = threadIdx.x, l = tid & 31, wid = tid >> 5;
    const int bhidx = blockIdx.y;
    const int b = bhidx >> 4, h = bhidx & 15, kvh = h >> 2;

    const __half* kp = QKV + (size_t)(b * SEQ) * QKVW + DMODEL + kvh * HDIM;

    auto issue_kv = [&](int kbase, int stg) {
        const uint32_t sbase = sb + A_KV + (uint32_t)stg * A_KVSTG;
        #pragma unroll
        for (int j = 0; j < 4; j++) {
            int s = tid + j * 256;
            int row = s >> 4, c = s & 15;
            size_t src = (size_t)(kbase + row) * QKVW + c * 8;
            uint32_t dst = (uint32_t)(row * AQROWB + c * 16);
            cp_async16(sbase + 0 * AKTILEB + dst, kp + src);          // K
            cp_async16(sbase + 1 * AKTILEB + dst, kp + src + 512);    // V
        }
    };

    const uint32_t laA = (uint32_t)((l & 15) * AQROWB + (l >> 4) * 16);
    const uint32_t laB = (uint32_t)(((((l >> 4) << 3) | (l & 7)) * AQROWB) + (((l >> 3) & 1) * 16));
    const uint32_t laV = (uint32_t)(((((l >> 3) & 1) * 8 + (l & 7)) * AQROWB) + ((l >> 4) * 16));

    #pragma unroll 1
    for (int pass = 0; pass < 2; pass++) {
        const int qtile = pass == 0 ? (int)blockIdx.x : (int)(15 - blockIdx.x);
        const int qbase = qtile * 128;

        __syncthreads();   // previous pass finished all smem reads

        // Q tile load
        {
            const __half* qh = QKV + ((size_t)(b * SEQ + qbase)) * QKVW + h * HDIM;
            #pragma unroll
            for (int j = 0; j < 8; j++) {
                int s = tid + j * 256;
                int row = s >> 4, c = s & 15;
                size_t src = (size_t)row * QKVW + c * 8;
                uint32_t dst = (uint32_t)(row * AQROWB + c * 16);
                *(uint4*)(smem + A_SQ + dst) = *(const uint4*)(qh + src);
            }
        }

        issue_kv(0, 0);
        cp_commit();

        float o[16][4] = {};
        float rm0 = -1e30f, rm1 = -1e30f, lp0 = 0.f, lp1 = 0.f;
        const int ktiles = 2 * qtile + 2;

        for (int kt = 0; kt < ktiles; kt++) {
            const int kbase = kt * 64;
            cp_wait<0>();
            __syncthreads();
            if (kt + 1 < ktiles) { issue_kv((kt + 1) * 64, (kt + 1) & 1); cp_commit(); }

            const uint32_t kvb = sb + A_KV + (uint32_t)(kt & 1) * A_KVSTG;
            const uint32_t sKH = kvb, sVH = kvb + AKTILEB;

            // ---- S = Q K^T (log2 domain; K pre-scaled) ----
            float s_[8][4] = {};
            #pragma unroll
            for (int ks = 0; ks < 8; ks++) {
                const uint32_t koff = ks * 32;
                uint32_t aq[4];
                uint32_t ra = (uint32_t)((wid * 16) * AQROWB) + koff;
                ldsm_x4(aq, sb + A_SQ + ra + laA);
                #pragma unroll
                for (int nj2 = 0; nj2 < 4; nj2++) {
                    uint32_t rb = (uint32_t)((nj2 * 16) * AQROWB) + koff + laB;
                    uint32_t th[4];
                    ldsm_x4(th, sKH + rb);
                    mma_f16(s_[2 * nj2],     aq, th);
                    mma_f16(s_[2 * nj2 + 1], aq, th + 2);
                }
            }

            // ---- causal mask ----
            const int qrow0 = qbase + wid * 16 + (l >> 2);
            if (kbase + 63 > qbase + wid * 16) {
                #pragma unroll
                for (int nj = 0; nj < 8; nj++) {
                    int kp2 = kbase + nj * 8 + (l & 3) * 2;
                    if (kp2     > qrow0)     s_[nj][0] = -1e30f;
                    if (kp2 + 1 > qrow0)     s_[nj][1] = -1e30f;
                    if (kp2     > qrow0 + 8) s_[nj][2] = -1e30f;
                    if (kp2 + 1 > qrow0 + 8) s_[nj][3] = -1e30f;
                }
            }

            // ---- online softmax (exp2 domain) ----
            float mx0 = -1e30f, mx1 = -1e30f;
            #pragma unroll
            for (int nj = 0; nj < 8; nj++) {
                mx0 = fmaxf(mx0, fmaxf(s_[nj][0], s_[nj][1]));
                mx1 = fmaxf(mx1, fmaxf(s_[nj][2], s_[nj][3]));
            }
            mx0 = fmaxf(mx0, __shfl_xor_sync(0xffffffffu, mx0, 1));
            mx0 = fmaxf(mx0, __shfl_xor_sync(0xffffffffu, mx0, 2));
            mx1 = fmaxf(mx1, __shfl_xor_sync(0xffffffffu, mx1, 1));
            mx1 = fmaxf(mx1, __shfl_xor_sync(0xffffffffu, mx1, 2));
            float nm0 = fmaxf(rm0, mx0), nm1 = fmaxf(rm1, mx1);

            bool changed = (nm0 != rm0) | (nm1 != rm1);
            if (__any_sync(0xffffffffu, changed)) {
                float al0 = exp2f(rm0 - nm0), al1 = exp2f(rm1 - nm1);
                lp0 *= al0; lp1 *= al1;
                #pragma unroll
                for (int dj = 0; dj < 16; dj++) {
                    o[dj][0] *= al0; o[dj][1] *= al0;
                    o[dj][2] *= al1; o[dj][3] *= al1;
                }
                rm0 = nm0; rm1 = nm1;
            }

            float ps0 = 0.f, ps1 = 0.f;
            #pragma unroll
            for (int nj = 0; nj < 8; nj++) {
                s_[nj][0] = exp2f(s_[nj][0] - rm0);
                s_[nj][1] = exp2f(s_[nj][1] - rm0);
                s_[nj][2] = exp2f(s_[nj][2] - rm1);
                s_[nj][3] = exp2f(s_[nj][3] - rm1);
                ps0 += s_[nj][0] + s_[nj][1];
                ps1 += s_[nj][2] + s_[nj][3];
            }
            lp0 += ps0;
            lp1 += ps1;

            // ---- O += P V ----
            #pragma unroll
            for (int kks = 0; kks < 4; kks++) {
                uint32_t ap[4];
                {
                    const float* p0 = s_[2 * kks];
                    const float* p1 = s_[2 * kks + 1];
                    ap[0] = h2_as_u32(__floats2half2_rn(p0[0], p0[1]));
                    ap[1] = h2_as_u32(__floats2half2_rn(p0[2], p0[3]));
                    ap[2] = h2_as_u32(__floats2half2_rn(p1[0], p1[1]));
                    ap[3] = h2_as_u32(__floats2half2_rn(p1[2], p1[3]));
                }
                uint32_t rvb = (uint32_t)((kks * 16) * AQROWB) + laV;
                #pragma unroll
                for (int dj2 = 0; dj2 < 8; dj2++) {
                    uint32_t coff = dj2 * 32;
                    uint32_t tv[4];
                    ldsm_x4_t(tv, sVH + rvb + coff);
                    mma_f16(o[2 * dj2],     ap, tv);
                    mma_f16(o[2 * dj2 + 1], ap, tv + 2);
                }
            }
        }

        // ---- finalize this qtile ----
        lp0 += __shfl_xor_sync(0xffffffffu, lp0, 1);
        lp0 += __shfl_xor_sync(0xffffffffu, lp0, 2);
        lp1 += __shfl_xor_sync(0xffffffffu, lp1, 1);
        lp1 += __shfl_xor_sync(0xffffffffu, lp1, 2);
        float inv0 = 1.0f / lp0, inv1 = 1.0f / lp1;

        const size_t row0 = (size_t)(b * SEQ + qbase + wid * 16 + (l >> 2));
        const int colb = h * HDIM + (l & 3) * 2;
        #pragma unroll
        for (int dj = 0; dj < 16; dj++) {
            int col = colb + dj * 8;
            *(__half2*)(Yh + row0 * DMODEL + col) =
                __floats2half2_rn(o[dj][0] * inv0, o[dj][1] * inv0);
            *(__half2*)(Yh + (row0 + 8) * DMODEL + col) =
                __floats2half2_rn(o[dj][2] * inv1, o[dj][3] * inv1);
        }
    }
}

// ---------------------------------------------------------------------------
extern "C" void kernel_launch(void* const* d_in, const int* in_sizes, int n_in,
                              void* d_out, int out_size)
{
    (void)in_sizes; (void)n_in; (void)out_size;
    const float* x     = (const float*)d_in[0];
    const float* Wq    = (const float*)d_in[1];
    const float* Wkv   = (const float*)d_in[2];
    const float* Wproj = (const float*)d_in[3];
    float* out = (float*)d_out;

    __half *xh, *wh, *wph, *qkvh, *yh;
    cudaGetSymbolAddress((void**)&xh,   g_xh);
    cudaGetSymbolAddress((void**)&wh,   g_wh);
    cudaGetSymbolAddress((void**)&wph,  g_wph);
    cudaGetSymbolAddress((void**)&qkvh, g_qkvh);
    cudaGetSymbolAddress((void**)&yh,   g_yh);

    cudaFuncSetAttribute(gemm_mma<true>,  cudaFuncAttributeMaxDynamicSharedMemorySize, G_SMEM);
    cudaFuncSetAttribute(gemm_mma<false>, cudaFuncAttributeMaxDynamicSharedMemorySize, G_SMEM);
    cudaFuncSetAttribute(attn_mma, cudaFuncAttributeMaxDynamicSharedMemorySize, A_SMEM);

    // 0) all fp32->fp16 conversions in one launch (4 float4 per thread)
    cvt_all<<<(CVT_TOTAL + 1023) / 1024, 256>>>(x, Wq, Wkv, Wproj, xh, wh, wph);

    // 1) fused QKV = x [Wq;Wkv]^T  -> fp16 [4096, 3072]
    gemm_mma<true><<<dim3(QKVW / 256, MTOT / 128), 256, G_SMEM>>>(xh, wh, qkvh,
                                                                  MTOT, QKVW, DMODEL);

    // 2) in-place RoPE on q heads (0..15) and k heads (16..19, scale folded)
    {
        int total = MTOT * (NHEAD + NKV) * (HDIM / 2);
        rope16<<<(total + 255) / 256, 256>>>(qkvh, QKVW, NHEAD + NKV);
    }

    // 3) attention -> yh (fp16), balanced qtile pairs
    attn_mma<<<dim3(SEQ / 256, BATCH * NHEAD), 256, A_SMEM>>>(qkvh, yh);

    // 4) out = y Wproj^T (fp32)
    gemm_mma<false><<<dim3(DMODEL / 256, MTOT / 128), 256, G_SMEM>>>(yh, wph, out,
                                                                     MTOT, DMODEL, DMODEL);
}

// round 12
// speedup vs baseline: 1.0869x; 1.0869x over previous
#include <cuda_runtime.h>
#include <cuda_fp16.h>
#include <cstdint>
#include <math.h>

#define BATCH  2
#define SEQ    2048
#define DMODEL 2048
#define NHEAD  16
#define NKV    4
#define HDIM   128
#define KVDIM  1024
#define QKVW   3072            // fused q|k|v row width
#define MTOT   4096

#define SCALE_LOG2E 0.12751589542466683f   // (1/sqrt(128)) * log2(e)

// ---------------- scratch ----------------
__device__ __half g_xh  [(size_t)MTOT * DMODEL];
__device__ __half g_wh  [(size_t)QKVW * DMODEL];     // [Wq; Wkv] fp16
__device__ __half g_wph [(size_t)DMODEL * DMODEL];
__device__ __half g_qkvh[(size_t)MTOT * QKVW];       // fused q|k|v fp16
__device__ __half g_yh  [(size_t)MTOT * DMODEL];

// ---------------- helpers ----------------
__device__ __forceinline__ uint32_t smem_u32(const void* p) {
    uint32_t a;
    asm("{ .reg .u64 t; cvta.to.shared.u64 t, %1; cvt.u32.u64 %0, t; }" : "=r"(a) : "l"(p));
    return a;
}
__device__ __forceinline__ void ldsm_x4(uint32_t* r, uint32_t addr) {
    asm volatile("ldmatrix.sync.aligned.m8n8.x4.shared.b16 {%0,%1,%2,%3}, [%4];"
                 : "=r"(r[0]), "=r"(r[1]), "=r"(r[2]), "=r"(r[3]) : "r"(addr));
}
__device__ __forceinline__ void ldsm_x4_t(uint32_t* r, uint32_t addr) {
    asm volatile("ldmatrix.sync.aligned.m8n8.x4.trans.shared.b16 {%0,%1,%2,%3}, [%4];"
                 : "=r"(r[0]), "=r"(r[1]), "=r"(r[2]), "=r"(r[3]) : "r"(addr));
}
__device__ __forceinline__ void mma_f16(float* d, const uint32_t* a, const uint32_t* b) {
    asm volatile(
        "mma.sync.aligned.m16n8k16.row.col.f32.f16.f16.f32 "
        "{%0,%1,%2,%3}, {%4,%5,%6,%7}, {%8,%9}, {%0,%1,%2,%3};"
        : "+f"(d[0]), "+f"(d[1]), "+f"(d[2]), "+f"(d[3])
        : "r"(a[0]), "r"(a[1]), "r"(a[2]), "r"(a[3]), "r"(b[0]), "r"(b[1]));
}
__device__ __forceinline__ uint32_t h2_as_u32(__half2 v) {
    return *reinterpret_cast<uint32_t*>(&v);
}
__device__ __forceinline__ void cp_async16(uint32_t dst, const void* src) {
    asm volatile("cp.async.cg.shared.global [%0], [%1], 16;" :: "r"(dst), "l"(src));
}
__device__ __forceinline__ void cp_commit() {
    asm volatile("cp.async.commit_group;" ::: "memory");
}
template <int N>
__device__ __forceinline__ void cp_wait() {
    asm volatile("cp.async.wait_group %0;" :: "n"(N) : "memory");
}

// ---------------- single fused fp32 -> fp16 conversion pass (MLP=4) --------
#define CVT_N1 (MTOT * DMODEL / 4)          // x
#define CVT_N2 (DMODEL * DMODEL / 4)        // Wq
#define CVT_N3 (KVDIM * DMODEL / 4)         // Wkv
#define CVT_N4 (DMODEL * DMODEL / 4)        // Wproj
#define CVT_TOTAL (CVT_N1 + CVT_N2 + CVT_N3 + CVT_N4)

__global__ void cvt_all(const float* __restrict__ x,   const float* __restrict__ wq,
                        const float* __restrict__ wkv, const float* __restrict__ wp,
                        __half* __restrict__ xh, __half* __restrict__ wh,
                        __half* __restrict__ wph)
{
    int stride = gridDim.x * blockDim.x;
    int i0 = blockIdx.x * blockDim.x + threadIdx.x;
    #pragma unroll
    for (int u = 0; u < 4; u++) {
        int i = i0 + u * stride;
        if (i >= CVT_TOTAL) return;
        const float* src;
        __half* dst;
        int j;
        if (i < CVT_N1)                        { src = x;   dst = xh;  j = i; }
        else if (i < CVT_N1 + CVT_N2)          { src = wq;  dst = wh;  j = i - CVT_N1; }
        else if (i < CVT_N1 + CVT_N2 + CVT_N3) { src = wkv; dst = wh + (size_t)DMODEL * DMODEL;
                                                 j = i - CVT_N1 - CVT_N2; }
        else                                   { src = wp;  dst = wph; j = i - CVT_N1 - CVT_N2 - CVT_N3; }
        float4 v = ((const float4*)src)[j];
        union { __half b[4]; uint2 u2; } H;
        H.b[0] = __float2half_rn(v.x); H.b[1] = __float2half_rn(v.y);
        H.b[2] = __float2half_rn(v.z); H.b[3] = __float2half_rn(v.w);
        ((uint2*)dst)[j] = H.u2;
    }
}

// ---------------- in-place fp16 RoPE; k heads (>=NHEAD) get scale folded ----
#define LOG2_10000_OVER64 0.20762050593046938f   // log2(10000)/64

__global__ void rope16(__half* __restrict__ buf, int rowstride, int nheads)
{
    int idx = blockIdx.x * blockDim.x + threadIdx.x;
    int total = MTOT * nheads * (HDIM / 2);
    if (idx >= total) return;
    int j = idx & 63;
    int h = (idx >> 6) % nheads;
    int m = idx / (64 * nheads);
    int t = m & (SEQ - 1);
    float inv_freq = exp2f(-(float)j * LOG2_10000_OVER64);
    float ang = (float)t * inv_freq;
    float s, c;
    sincosf(ang, &s, &c);
    float post = (h >= NHEAD) ? SCALE_LOG2E : 1.0f;
    size_t o = (size_t)m * rowstride + h * HDIM;
    float x1 = __half2float(buf[o + j]);
    float x2 = __half2float(buf[o + j + 64]);
    buf[o + j]      = __float2half_rn((x1 * c - x2 * s) * post);
    buf[o + j + 64] = __float2half_rn((x2 * c + x1 * s) * post);
}

// ---------------------------------------------------------------------------
// HMMA fp16 NT GEMM (R10 proven config): CTA 128x128, BK=64, 8 warps (4m x 2n),
// cp.async 3-stage, 2 CTA/SM. Row pitch 144B.
// ---------------------------------------------------------------------------
#define GBK     64
#define G_ROWB  144
#define G_TILEB (128 * G_ROWB)     // 18432
#define G_STGB  (2 * G_TILEB)      // 36864
#define G_SMEM  (3 * G_STGB)       // 110592

template <bool HALF_OUT>
__global__ __launch_bounds__(256, 2)
void gemm_mma(const __half* __restrict__ A, const __half* __restrict__ B,
              void* __restrict__ Cv, int M, int N, int K)
{
    extern __shared__ char smem[];
    const uint32_t sb0 = smem_u32(smem);
    const int tid = threadIdx.x, l = tid & 31, wid = tid >> 5;
    const int wm = wid & 3, wn = wid >> 2;
    const int mbase = blockIdx.y * 128, nbase = blockIdx.x * 128;

    const int g_row = tid >> 3;          // 0..31
    const int g_c   = tid & 7;           // 16B chunk within 128B row

    const uint32_t laA = (uint32_t)((l & 15) * G_ROWB + (l >> 4) * 16);
    const uint32_t laB = (uint32_t)(((((l >> 4) << 3) | (l & 7)) * G_ROWB) + (((l >> 3) & 1) * 16));

    float acc[2][8][4] = {};

    auto issue = [&](int kb, int stg) {
        const uint32_t sb = sb0 + (uint32_t)stg * G_STGB;
        #pragma unroll
        for (int j = 0; j < 4; j++) {
            int row = g_row + j * 32;
            uint32_t dst = (uint32_t)(row * G_ROWB + g_c * 16);
            size_t sa  = (size_t)(mbase + row) * K + kb + g_c * 8;
            size_t sbg = (size_t)(nbase + row) * K + kb + g_c * 8;
            cp_async16(sb + dst, A + sa);
            cp_async16(sb + G_TILEB + dst, B + sbg);
        }
    };

    const int NC = K / GBK;
    issue(0, 0); cp_commit();
    issue(GBK, 1); cp_commit();

    int stg = 0;
    for (int i = 0; i < NC; i++) {
        cp_wait<1>();
        __syncthreads();
        {
            int s2 = stg + 2; if (s2 >= 3) s2 -= 3;
            if (i + 2 < NC) issue((i + 2) * GBK, s2);
            cp_commit();
        }

        const uint32_t base = sb0 + (uint32_t)stg * G_STGB;
        const uint32_t sA = base, sB = base + G_TILEB;
        #pragma unroll
        for (int ks = 0; ks < 4; ks++) {
            const uint32_t koff = ks * 32;
            uint32_t af[2][4];
            #pragma unroll
            for (int mi = 0; mi < 2; mi++) {
                uint32_t ra = (uint32_t)((wm * 32 + mi * 16) * G_ROWB) + koff + laA;
                ldsm_x4(af[mi], sA + ra);
            }
            #pragma unroll
            for (int nj2 = 0; nj2 < 4; nj2++) {
                uint32_t rb = (uint32_t)(((wn * 64) + nj2 * 16) * G_ROWB) + koff + laB;
                uint32_t bf[4];
                ldsm_x4(bf, sB + rb);
                #pragma unroll
                for (int mi = 0; mi < 2; mi++) {
                    mma_f16(acc[mi][2 * nj2],     af[mi], bf);
                    mma_f16(acc[mi][2 * nj2 + 1], af[mi], bf + 2);
                }
            }
        }
        if (++stg == 3) stg = 0;
    }

    #pragma unroll
    for (int mi = 0; mi < 2; mi++) {
        int row = mbase + wm * 32 + mi * 16 + (l >> 2);
        #pragma unroll
        for (int nj = 0; nj < 8; nj++) {
            int col = nbase + wn * 64 + nj * 8 + (l & 3) * 2;
            if (HALF_OUT) {
                __half* C = (__half*)Cv;
                *(__half2*)&C[(size_t)row * N + col] =
                    __floats2half2_rn(acc[mi][nj][0], acc[mi][nj][1]);
                *(__half2*)&C[(size_t)(row + 8) * N + col] =
                    __floats2half2_rn(acc[mi][nj][2], acc[mi][nj][3]);
            } else {
                float* C = (float*)Cv;
                *(float2*)&C[(size_t)row * N + col] =
                    make_float2(acc[mi][nj][0], acc[mi][nj][1]);
                *(float2*)&C[(size_t)(row + 8) * N + col] =
                    make_float2(acc[mi][nj][2], acc[mi][nj][3]);
            }
        }
    }
}

// ---------------------------------------------------------------------------
// HMMA fp16 flash attention, causal, GQA; fused QKV input (row stride 3072).
// K pre-scaled by scale*log2e -> S in log2 domain.
// CTA q-tile 256 rows, 8 warps x 32 rows (2 m16 sub-tiles per warp), 1 CTA/SM.
// Grid (4, 32): CTA does 256-row qtile pair (i, 7-i) -> 36 kv-tiles each.
// ---------------------------------------------------------------------------
#define AQROWB  272
#define AQTILEB (256 * AQROWB)       // 69632 (256-row Q tile)
#define AKTILEB (64 * AQROWB)        // 17408
#define A_SQ    0
#define A_KV    (A_SQ + AQTILEB)
#define A_KVSTG (2 * AKTILEB)
#define A_SMEM  (A_KV + 2 * A_KVSTG) // 139264

__global__ __launch_bounds__(256, 1)
void attn_mma(const __half* __restrict__ QKV, __half* __restrict__ Yh)
{
    extern __shared__ char smem[];
    const uint32_t sb = smem_u32(smem);
    const int tid = threadIdx.x, l = tid & 31, wid = tid >> 5;
    const int bhidx = blockIdx.y;
    const int b = bhidx >> 4, h = bhidx & 15, kvh = h >> 2;

    const __half* kp = QKV + (size_t)(b * SEQ) * QKVW + DMODEL + kvh * HDIM;

    auto issue_kv = [&](int kbase, int stg) {
        const uint32_t sbase = sb + A_KV + (uint32_t)stg * A_KVSTG;
        #pragma unroll
        for (int j = 0; j < 4; j++) {
            int s = tid + j * 256;
            int row = s >> 4, c = s & 15;
            size_t src = (size_t)(kbase + row) * QKVW + c * 8;
            uint32_t dst = (uint32_t)(row * AQROWB + c * 16);
            cp_async16(sbase + 0 * AKTILEB + dst, kp + src);          // K
            cp_async16(sbase + 1 * AKTILEB + dst, kp + src + 512);    // V
        }
    };

    const uint32_t laA = (uint32_t)((l & 15) * AQROWB + (l >> 4) * 16);
    const uint32_t laB = (uint32_t)(((((l >> 4) << 3) | (l & 7)) * AQROWB) + (((l >> 3) & 1) * 16));
    const uint32_t laV = (uint32_t)(((((l >> 3) & 1) * 8 + (l & 7)) * AQROWB) + ((l >> 4) * 16));

    #pragma unroll 1
    for (int pass = 0; pass < 2; pass++) {
        const int qtile = pass == 0 ? (int)blockIdx.x : (int)(7 - blockIdx.x);
        const int qbase = qtile * 256;

        __syncthreads();   // previous pass finished all smem reads

        // Q tile load: 256 rows x 128 cols
        {
            const __half* qh = QKV + ((size_t)(b * SEQ + qbase)) * QKVW + h * HDIM;
            #pragma unroll
            for (int j = 0; j < 16; j++) {
                int s = tid + j * 256;
                int row = s >> 4, c = s & 15;
                size_t src = (size_t)row * QKVW + c * 8;
                uint32_t dst = (uint32_t)(row * AQROWB + c * 16);
                *(uint4*)(smem + A_SQ + dst) = *(const uint4*)(qh + src);
            }
        }

        issue_kv(0, 0);
        cp_commit();

        float o[2][16][4] = {};
        float rm[4] = {-1e30f, -1e30f, -1e30f, -1e30f};
        float lp[4] = {};
        const int ktiles = 4 * qtile + 4;

        for (int kt = 0; kt < ktiles; kt++) {
            const int kbase = kt * 64;
            cp_wait<0>();
            __syncthreads();
            if (kt + 1 < ktiles) { issue_kv((kt + 1) * 64, (kt + 1) & 1); cp_commit(); }

            const uint32_t kvb = sb + A_KV + (uint32_t)(kt & 1) * A_KVSTG;
            const uint32_t sKH = kvb, sVH = kvb + AKTILEB;

            // ---- S = Q K^T for both 16-row sub-tiles ----
            float s_[2][8][4] = {};
            #pragma unroll
            for (int ks = 0; ks < 8; ks++) {
                const uint32_t koff = ks * 32;
                uint32_t aq[2][4];
                uint32_t ra0 = (uint32_t)((wid * 32) * AQROWB) + koff + laA;
                ldsm_x4(aq[0], sb + A_SQ + ra0);
                ldsm_x4(aq[1], sb + A_SQ + ra0 + (uint32_t)(16 * AQROWB));
                #pragma unroll
                for (int nj2 = 0; nj2 < 4; nj2++) {
                    uint32_t rb = (uint32_t)((nj2 * 16) * AQROWB) + koff + laB;
                    uint32_t th[4];
                    ldsm_x4(th, sKH + rb);
                    #pragma unroll
                    for (int mi = 0; mi < 2; mi++) {
                        mma_f16(s_[mi][2 * nj2],     aq[mi], th);
                        mma_f16(s_[mi][2 * nj2 + 1], aq[mi], th + 2);
                    }
                }
            }

            // ---- causal mask ----
            const int qr = qbase + wid * 32 + (l >> 2);   // sub-tile 0, rows qr / qr+8
            if (kbase + 63 > qbase + wid * 32) {
                #pragma unroll
                for (int mi = 0; mi < 2; mi++) {
                    int r0 = qr + mi * 16;
                    #pragma unroll
                    for (int nj = 0; nj < 8; nj++) {
                        int kp2 = kbase + nj * 8 + (l & 3) * 2;
                        if (kp2     > r0)     s_[mi][nj][0] = -1e30f;
                        if (kp2 + 1 > r0)     s_[mi][nj][1] = -1e30f;
                        if (kp2     > r0 + 8) s_[mi][nj][2] = -1e30f;
                        if (kp2 + 1 > r0 + 8) s_[mi][nj][3] = -1e30f;
                    }
                }
            }

            // ---- online softmax (exp2 domain), 4 rows per thread ----
            float mx[4] = {-1e30f, -1e30f, -1e30f, -1e30f};
            #pragma unroll
            for (int mi = 0; mi < 2; mi++)
                #pragma unroll
                for (int nj = 0; nj < 8; nj++) {
                    mx[2 * mi]     = fmaxf(mx[2 * mi],     fmaxf(s_[mi][nj][0], s_[mi][nj][1]));
                    mx[2 * mi + 1] = fmaxf(mx[2 * mi + 1], fmaxf(s_[mi][nj][2], s_[mi][nj][3]));
                }
            #pragma unroll
            for (int r = 0; r < 4; r++) {
                mx[r] = fmaxf(mx[r], __shfl_xor_sync(0xffffffffu, mx[r], 1));
                mx[r] = fmaxf(mx[r], __shfl_xor_sync(0xffffffffu, mx[r], 2));
            }
            float nm[4];
            bool changed = false;
            #pragma unroll
            for (int r = 0; r < 4; r++) {
                nm[r] = fmaxf(rm[r], mx[r]);
                changed |= (nm[r] != rm[r]);
            }
            if (__any_sync(0xffffffffu, changed)) {
                float al[4];
                #pragma unroll
                for (int r = 0; r < 4; r++) {
                    al[r] = exp2f(rm[r] - nm[r]);
                    lp[r] *= al[r];
                    rm[r] = nm[r];
                }
                #pragma unroll
                for (int mi = 0; mi < 2; mi++)
                    #pragma unroll
                    for (int dj = 0; dj < 16; dj++) {
                        o[mi][dj][0] *= al[2 * mi];     o[mi][dj][1] *= al[2 * mi];
                        o[mi][dj][2] *= al[2 * mi + 1]; o[mi][dj][3] *= al[2 * mi + 1];
                    }
            }

            #pragma unroll
            for (int mi = 0; mi < 2; mi++) {
                float ps0 = 0.f, ps1 = 0.f;
                #pragma unroll
                for (int nj = 0; nj < 8; nj++) {
                    s_[mi][nj][0] = exp2f(s_[mi][nj][0] - rm[2 * mi]);
                    s_[mi][nj][1] = exp2f(s_[mi][nj][1] - rm[2 * mi]);
                    s_[mi][nj][2] = exp2f(s_[mi][nj][2] - rm[2 * mi + 1]);
                    s_[mi][nj][3] = exp2f(s_[mi][nj][3] - rm[2 * mi + 1]);
                    ps0 += s_[mi][nj][0] + s_[mi][nj][1];
                    ps1 += s_[mi][nj][2] + s_[mi][nj][3];
                }
                lp[2 * mi]     += ps0;
                lp[2 * mi + 1] += ps1;
            }

            // ---- O += P V (V frags shared across both sub-tiles) ----
            #pragma unroll
            for (int kks = 0; kks < 4; kks++) {
                uint32_t ap[2][4];
                #pragma unroll
                for (int mi = 0; mi < 2; mi++) {
                    const float* p0 = s_[mi][2 * kks];
                    const float* p1 = s_[mi][2 * kks + 1];
                    ap[mi][0] = h2_as_u32(__floats2half2_rn(p0[0], p0[1]));
                    ap[mi][1] = h2_as_u32(__floats2half2_rn(p0[2], p0[3]));
                    ap[mi][2] = h2_as_u32(__floats2half2_rn(p1[0], p1[1]));
                    ap[mi][3] = h2_as_u32(__floats2half2_rn(p1[2], p1[3]));
                }
                uint32_t rvb = (uint32_t)((kks * 16) * AQROWB) + laV;
                #pragma unroll
                for (int dj2 = 0; dj2 < 8; dj2++) {
                    uint32_t coff = dj2 * 32;
                    uint32_t tv[4];
                    ldsm_x4_t(tv, sVH + rvb + coff);
                    #pragma unroll
                    for (int mi = 0; mi < 2; mi++) {
                        mma_f16(o[mi][2 * dj2],     ap[mi], tv);
                        mma_f16(o[mi][2 * dj2 + 1], ap[mi], tv + 2);
                    }
                }
            }
        }

        // ---- finalize this qtile ----
        #pragma unroll
        for (int r = 0; r < 4; r++) {
            lp[r] += __shfl_xor_sync(0xffffffffu, lp[r], 1);
            lp[r] += __shfl_xor_sync(0xffffffffu, lp[r], 2);
        }
        float inv[4] = {1.0f / lp[0], 1.0f / lp[1], 1.0f / lp[2], 1.0f / lp[3]};

        const int colb = h * HDIM + (l & 3) * 2;
        #pragma unroll
        for (int mi = 0; mi < 2; mi++) {
            size_t row0 = (size_t)(b * SEQ + qbase + wid * 32 + mi * 16 + (l >> 2));
            #pragma unroll
            for (int dj = 0; dj < 16; dj++) {
                int col = colb + dj * 8;
                *(__half2*)(Yh + row0 * DMODEL + col) =
                    __floats2half2_rn(o[mi][dj][0] * inv[2 * mi], o[mi][dj][1] * inv[2 * mi]);
                *(__half2*)(Yh + (row0 + 8) * DMODEL + col) =
                    __floats2half2_rn(o[mi][dj][2] * inv[2 * mi + 1], o[mi][dj][3] * inv[2 * mi + 1]);
            }
        }
    }
}

// ---------------------------------------------------------------------------
extern "C" void kernel_launch(void* const* d_in, const int* in_sizes, int n_in,
                              void* d_out, int out_size)
{
    (void)in_sizes; (void)n_in; (void)out_size;
    const float* x     = (const float*)d_in[0];
    const float* Wq    = (const float*)d_in[1];
    const float* Wkv   = (const float*)d_in[2];
    const float* Wproj = (const float*)d_in[3];
    float* out = (float*)d_out;

    __half *xh, *wh, *wph, *qkvh, *yh;
    cudaGetSymbolAddress((void**)&xh,   g_xh);
    cudaGetSymbolAddress((void**)&wh,   g_wh);
    cudaGetSymbolAddress((void**)&wph,  g_wph);
    cudaGetSymbolAddress((void**)&qkvh, g_qkvh);
    cudaGetSymbolAddress((void**)&yh,   g_yh);

    cudaFuncSetAttribute(gemm_mma<true>,  cudaFuncAttributeMaxDynamicSharedMemorySize, G_SMEM);
    cudaFuncSetAttribute(gemm_mma<false>, cudaFuncAttributeMaxDynamicSharedMemorySize, G_SMEM);
    cudaFuncSetAttribute(attn_mma, cudaFuncAttributeMaxDynamicSharedMemorySize, A_SMEM);

    // 0) all fp32->fp16 conversions in one launch (4 float4 per thread)
    cvt_all<<<(CVT_TOTAL + 1023) / 1024, 256>>>(x, Wq, Wkv, Wproj, xh, wh, wph);

    // 1) fused QKV = x [Wq;Wkv]^T  -> fp16 [4096, 3072]
    gemm_mma<true><<<dim3(QKVW / 128, MTOT / 128), 256, G_SMEM>>>(xh, wh, qkvh,
                                                                  MTOT, QKVW, DMODEL);

    // 2) in-place RoPE on q heads (0..15) and k heads (16..19, scale folded)
    {
        int total = MTOT * (NHEAD + NKV) * (HDIM / 2);
        rope16<<<(total + 255) / 256, 256>>>(qkvh, QKVW, NHEAD + NKV);
    }

    // 3) attention -> yh (fp16), 256-row qtile pairs, grid (4, 32)
    attn_mma<<<dim3(SEQ / 512, BATCH * NHEAD), 256, A_SMEM>>>(qkvh, yh);

    // 4) out = y Wproj^T (fp32)
    gemm_mma<false><<<dim3(DMODEL / 128, MTOT / 128), 256, G_SMEM>>>(yh, wph, out,
                                                                     MTOT, DMODEL, DMODEL);
}

// round 13
// speedup vs baseline: 1.1283x; 1.0381x over previous
#include <cuda_runtime.h>
#include <cuda_fp16.h>
#include <cstdint>
#include <math.h>

#define BATCH  2
#define SEQ    2048
#define DMODEL 2048
#define NHEAD  16
#define NKV    4
#define HDIM   128
#define KVDIM  1024
#define QKVW   3072            // fused q|k|v row width
#define MTOT   4096

#define SCALE_LOG2E 0.12751589542466683f   // (1/sqrt(128)) * log2(e)

// ---------------- scratch ----------------
__device__ __half g_xh  [(size_t)MTOT * DMODEL];
__device__ __half g_wh  [(size_t)QKVW * DMODEL];     // [Wq; Wkv] fp16
__device__ __half g_wph [(size_t)DMODEL * DMODEL];
__device__ __half g_qkvh[(size_t)MTOT * QKVW];       // fused q|k|v fp16
__device__ __half g_yh  [(size_t)MTOT * DMODEL];

// ---------------- helpers ----------------
__device__ __forceinline__ uint32_t smem_u32(const void* p) {
    uint32_t a;
    asm("{ .reg .u64 t; cvta.to.shared.u64 t, %1; cvt.u32.u64 %0, t; }" : "=r"(a) : "l"(p));
    return a;
}
__device__ __forceinline__ void ldsm_x4(uint32_t* r, uint32_t addr) {
    asm volatile("ldmatrix.sync.aligned.m8n8.x4.shared.b16 {%0,%1,%2,%3}, [%4];"
                 : "=r"(r[0]), "=r"(r[1]), "=r"(r[2]), "=r"(r[3]) : "r"(addr));
}
__device__ __forceinline__ void ldsm_x4_t(uint32_t* r, uint32_t addr) {
    asm volatile("ldmatrix.sync.aligned.m8n8.x4.trans.shared.b16 {%0,%1,%2,%3}, [%4];"
                 : "=r"(r[0]), "=r"(r[1]), "=r"(r[2]), "=r"(r[3]) : "r"(addr));
}
__device__ __forceinline__ void mma_f16(float* d, const uint32_t* a, const uint32_t* b) {
    asm volatile(
        "mma.sync.aligned.m16n8k16.row.col.f32.f16.f16.f32 "
        "{%0,%1,%2,%3}, {%4,%5,%6,%7}, {%8,%9}, {%0,%1,%2,%3};"
        : "+f"(d[0]), "+f"(d[1]), "+f"(d[2]), "+f"(d[3])
        : "r"(a[0]), "r"(a[1]), "r"(a[2]), "r"(a[3]), "r"(b[0]), "r"(b[1]));
}
__device__ __forceinline__ uint32_t h2_as_u32(__half2 v) {
    return *reinterpret_cast<uint32_t*>(&v);
}
__device__ __forceinline__ void cp_async16(uint32_t dst, const void* src) {
    asm volatile("cp.async.cg.shared.global [%0], [%1], 16;" :: "r"(dst), "l"(src));
}
__device__ __forceinline__ void cp_commit() {
    asm volatile("cp.async.commit_group;" ::: "memory");
}
template <int N>
__device__ __forceinline__ void cp_wait() {
    asm volatile("cp.async.wait_group %0;" :: "n"(N) : "memory");
}
__device__ __forceinline__ float ex2(float x) {
    float y;
    asm("ex2.approx.f32 %0, %1;" : "=f"(y) : "f"(x));
    return y;
}

// ---------------- single fused fp32 -> fp16 conversion pass (MLP=4) --------
#define CVT_N1 (MTOT * DMODEL / 4)          // x
#define CVT_N2 (DMODEL * DMODEL / 4)        // Wq
#define CVT_N3 (KVDIM * DMODEL / 4)         // Wkv
#define CVT_N4 (DMODEL * DMODEL / 4)        // Wproj
#define CVT_TOTAL (CVT_N1 + CVT_N2 + CVT_N3 + CVT_N4)

__global__ void cvt_all(const float* __restrict__ x,   const float* __restrict__ wq,
                        const float* __restrict__ wkv, const float* __restrict__ wp,
                        __half* __restrict__ xh, __half* __restrict__ wh,
                        __half* __restrict__ wph)
{
    int stride = gridDim.x * blockDim.x;
    int i0 = blockIdx.x * blockDim.x + threadIdx.x;
    #pragma unroll
    for (int u = 0; u < 4; u++) {
        int i = i0 + u * stride;
        if (i >= CVT_TOTAL) return;
        const float* src;
        __half* dst;
        int j;
        if (i < CVT_N1)                        { src = x;   dst = xh;  j = i; }
        else if (i < CVT_N1 + CVT_N2)          { src = wq;  dst = wh;  j = i - CVT_N1; }
        else if (i < CVT_N1 + CVT_N2 + CVT_N3) { src = wkv; dst = wh + (size_t)DMODEL * DMODEL;
                                                 j = i - CVT_N1 - CVT_N2; }
        else                                   { src = wp;  dst = wph; j = i - CVT_N1 - CVT_N2 - CVT_N3; }
        float4 v = ((const float4*)src)[j];
        union { __half b[4]; uint2 u2; } H;
        H.b[0] = __float2half_rn(v.x); H.b[1] = __float2half_rn(v.y);
        H.b[2] = __float2half_rn(v.z); H.b[3] = __float2half_rn(v.w);
        ((uint2*)dst)[j] = H.u2;
    }
}

// ---------------- in-place fp16 RoPE, vectorized; k heads get scale folded --
// Thread handles 8 consecutive j of one (row, head): uint4 in/out.
// tasks = MTOT * 20 heads * 8 jgroups = 655360
#define LOG2_10000_OVER64 0.20762050593046938f   // log2(10000)/64
#define ROPE_HEADS (NHEAD + NKV)                 // 20
#define ROPE_TASKS (MTOT * ROPE_HEADS * 8)

__global__ void rope16(__half* __restrict__ buf)
{
    int idx = blockIdx.x * blockDim.x + threadIdx.x;
    if (idx >= ROPE_TASKS) return;
    int jg   = idx & 7;
    int rest = idx >> 3;
    int h    = rest % ROPE_HEADS;
    int m    = rest / ROPE_HEADS;
    int t    = m & (SEQ - 1);
    float post = (h >= NHEAD) ? SCALE_LOG2E : 1.0f;

    size_t o = (size_t)m * QKVW + h * HDIM + jg * 8;
    union { uint4 v; __half b[8]; } X1, X2, Y1, Y2;
    X1.v = *(const uint4*)(buf + o);
    X2.v = *(const uint4*)(buf + o + 64);

    #pragma unroll
    for (int e = 0; e < 8; e++) {
        int j = jg * 8 + e;
        float inv_freq = ex2(-(float)j * LOG2_10000_OVER64);
        float ang = (float)t * inv_freq;
        float s, c;
        __sincosf(ang, &s, &c);
        float x1 = __half2float(X1.b[e]);
        float x2 = __half2float(X2.b[e]);
        Y1.b[e] = __float2half_rn((x1 * c - x2 * s) * post);
        Y2.b[e] = __float2half_rn((x2 * c + x1 * s) * post);
    }
    *(uint4*)(buf + o)      = Y1.v;
    *(uint4*)(buf + o + 64) = Y2.v;
}

// ---------------------------------------------------------------------------
// HMMA fp16 NT GEMM (proven config): CTA 128x128, BK=64, 8 warps (4m x 2n),
// cp.async 3-stage, 2 CTA/SM. Row pitch 144B.
// ---------------------------------------------------------------------------
#define GBK     64
#define G_ROWB  144
#define G_TILEB (128 * G_ROWB)     // 18432
#define G_STGB  (2 * G_TILEB)      // 36864
#define G_SMEM  (3 * G_STGB)       // 110592

template <bool HALF_OUT>
__global__ __launch_bounds__(256, 2)
void gemm_mma(const __half* __restrict__ A, const __half* __restrict__ B,
              void* __restrict__ Cv, int M, int N, int K)
{
    extern __shared__ char smem[];
    const uint32_t sb0 = smem_u32(smem);
    const int tid = threadIdx.x, l = tid & 31, wid = tid >> 5;
    const int wm = wid & 3, wn = wid >> 2;
    const int mbase = blockIdx.y * 128, nbase = blockIdx.x * 128;

    const int g_row = tid >> 3;          // 0..31
    const int g_c   = tid & 7;           // 16B chunk within 128B row

    const uint32_t laA = (uint32_t)((l & 15) * G_ROWB + (l >> 4) * 16);
    const uint32_t laB = (uint32_t)(((((l >> 4) << 3) | (l & 7)) * G_ROWB) + (((l >> 3) & 1) * 16));

    float acc[2][8][4] = {};

    auto issue = [&](int kb, int stg) {
        const uint32_t sb = sb0 + (uint32_t)stg * G_STGB;
        #pragma unroll
        for (int j = 0; j < 4; j++) {
            int row = g_row + j * 32;
            uint32_t dst = (uint32_t)(row * G_ROWB + g_c * 16);
            size_t sa  = (size_t)(mbase + row) * K + kb + g_c * 8;
            size_t sbg = (size_t)(nbase + row) * K + kb + g_c * 8;
            cp_async16(sb + dst, A + sa);
            cp_async16(sb + G_TILEB + dst, B + sbg);
        }
    };

    const int NC = K / GBK;
    issue(0, 0); cp_commit();
    issue(GBK, 1); cp_commit();

    int stg = 0;
    for (int i = 0; i < NC; i++) {
        cp_wait<1>();
        __syncthreads();
        {
            int s2 = stg + 2; if (s2 >= 3) s2 -= 3;
            if (i + 2 < NC) issue((i + 2) * GBK, s2);
            cp_commit();
        }

        const uint32_t base = sb0 + (uint32_t)stg * G_STGB;
        const uint32_t sA = base, sB = base + G_TILEB;
        #pragma unroll
        for (int ks = 0; ks < 4; ks++) {
            const uint32_t koff = ks * 32;
            uint32_t af[2][4];
            #pragma unroll
            for (int mi = 0; mi < 2; mi++) {
                uint32_t ra = (uint32_t)((wm * 32 + mi * 16) * G_ROWB) + koff + laA;
                ldsm_x4(af[mi], sA + ra);
            }
            #pragma unroll
            for (int nj2 = 0; nj2 < 4; nj2++) {
                uint32_t rb = (uint32_t)(((wn * 64) + nj2 * 16) * G_ROWB) + koff + laB;
                uint32_t bf[4];
                ldsm_x4(bf, sB + rb);
                #pragma unroll
                for (int mi = 0; mi < 2; mi++) {
                    mma_f16(acc[mi][2 * nj2],     af[mi], bf);
                    mma_f16(acc[mi][2 * nj2 + 1], af[mi], bf + 2);
                }
            }
        }
        if (++stg == 3) stg = 0;
    }

    #pragma unroll
    for (int mi = 0; mi < 2; mi++) {
        int row = mbase + wm * 32 + mi * 16 + (l >> 2);
        #pragma unroll
        for (int nj = 0; nj < 8; nj++) {
            int col = nbase + wn * 64 + nj * 8 + (l & 3) * 2;
            if (HALF_OUT) {
                __half* C = (__half*)Cv;
                *(__half2*)&C[(size_t)row * N + col] =
                    __floats2half2_rn(acc[mi][nj][0], acc[mi][nj][1]);
                *(__half2*)&C[(size_t)(row + 8) * N + col] =
                    __floats2half2_rn(acc[mi][nj][2], acc[mi][nj][3]);
            } else {
                float* C = (float*)Cv;
                *(float2*)&C[(size_t)row * N + col] =
                    make_float2(acc[mi][nj][0], acc[mi][nj][1]);
                *(float2*)&C[(size_t)(row + 8) * N + col] =
                    make_float2(acc[mi][nj][2], acc[mi][nj][3]);
            }
        }
    }
}

// ---------------------------------------------------------------------------
// HMMA fp16 flash attention, causal, GQA; fused QKV input (row stride 3072).
// K pre-scaled by scale*log2e -> S in log2 domain; ex2.approx softmax.
// CTA q-tile 256 rows, 8 warps x 32 rows, 1 CTA/SM. Grid (4, 32) pairs (i,7-i).
// ---------------------------------------------------------------------------
#define AQROWB  272
#define AQTILEB (256 * AQROWB)       // 69632
#define AKTILEB (64 * AQROWB)        // 17408
#define A_SQ    0
#define A_KV    (A_SQ + AQTILEB)
#define A_KVSTG (2 * AKTILEB)
#define A_SMEM  (A_KV + 2 * A_KVSTG) // 139264

__global__ __launch_bounds__(256, 1)
void attn_mma(const __half* __restrict__ QKV, __half* __restrict__ Yh)
{
    extern __shared__ char smem[];
    const uint32_t sb = smem_u32(smem);
    const int tid = threadIdx.x, l = tid & 31, wid = tid >> 5;
    const int bhidx = blockIdx.y;
    const int b = bhidx >> 4, h = bhidx & 15, kvh = h >> 2;

    const __half* kp = QKV + (size_t)(b * SEQ) * QKVW + DMODEL + kvh * HDIM;

    auto issue_kv = [&](int kbase, int stg) {
        const uint32_t sbase = sb + A_KV + (uint32_t)stg * A_KVSTG;
        #pragma unroll
        for (int j = 0; j < 4; j++) {
            int s = tid + j * 256;
            int row = s >> 4, c = s & 15;
            size_t src = (size_t)(kbase + row) * QKVW + c * 8;
            uint32_t dst = (uint32_t)(row * AQROWB + c * 16);
            cp_async16(sbase + 0 * AKTILEB + dst, kp + src);          // K
            cp_async16(sbase + 1 * AKTILEB + dst, kp + src + 512);    // V
        }
    };

    const uint32_t laA = (uint32_t)((l & 15) * AQROWB + (l >> 4) * 16);
    const uint32_t laB = (uint32_t)(((((l >> 4) << 3) | (l & 7)) * AQROWB) + (((l >> 3) & 1) * 16));
    const uint32_t laV = (uint32_t)(((((l >> 3) & 1) * 8 + (l & 7)) * AQROWB) + ((l >> 4) * 16));

    #pragma unroll 1
    for (int pass = 0; pass < 2; pass++) {
        const int qtile = pass == 0 ? (int)blockIdx.x : (int)(7 - blockIdx.x);
        const int qbase = qtile * 256;

        __syncthreads();   // previous pass finished all smem reads

        // Q tile load: 256 rows x 128 cols
        {
            const __half* qh = QKV + ((size_t)(b * SEQ + qbase)) * QKVW + h * HDIM;
            #pragma unroll
            for (int j = 0; j < 16; j++) {
                int s = tid + j * 256;
                int row = s >> 4, c = s & 15;
                size_t src = (size_t)row * QKVW + c * 8;
                uint32_t dst = (uint32_t)(row * AQROWB + c * 16);
                *(uint4*)(smem + A_SQ + dst) = *(const uint4*)(qh + src);
            }
        }

        issue_kv(0, 0);
        cp_commit();

        float o[2][16][4] = {};
        float rm[4] = {-1e30f, -1e30f, -1e30f, -1e30f};
        float lp[4] = {};
        const int ktiles = 4 * qtile + 4;

        for (int kt = 0; kt < ktiles; kt++) {
            const int kbase = kt * 64;
            cp_wait<0>();
            __syncthreads();
            if (kt + 1 < ktiles) { issue_kv((kt + 1) * 64, (kt + 1) & 1); cp_commit(); }

            const uint32_t kvb = sb + A_KV + (uint32_t)(kt & 1) * A_KVSTG;
            const uint32_t sKH = kvb, sVH = kvb + AKTILEB;

            // ---- S = Q K^T for both 16-row sub-tiles ----
            float s_[2][8][4] = {};
            #pragma unroll
            for (int ks = 0; ks < 8; ks++) {
                const uint32_t koff = ks * 32;
                uint32_t aq[2][4];
                uint32_t ra0 = (uint32_t)((wid * 32) * AQROWB) + koff + laA;
                ldsm_x4(aq[0], sb + A_SQ + ra0);
                ldsm_x4(aq[1], sb + A_SQ + ra0 + (uint32_t)(16 * AQROWB));
                #pragma unroll
                for (int nj2 = 0; nj2 < 4; nj2++) {
                    uint32_t rb = (uint32_t)((nj2 * 16) * AQROWB) + koff + laB;
                    uint32_t th[4];
                    ldsm_x4(th, sKH + rb);
                    #pragma unroll
                    for (int mi = 0; mi < 2; mi++) {
                        mma_f16(s_[mi][2 * nj2],     aq[mi], th);
                        mma_f16(s_[mi][2 * nj2 + 1], aq[mi], th + 2);
                    }
                }
            }

            // ---- causal mask ----
            const int qr = qbase + wid * 32 + (l >> 2);
            if (kbase + 63 > qbase + wid * 32) {
                #pragma unroll
                for (int mi = 0; mi < 2; mi++) {
                    int r0 = qr + mi * 16;
                    #pragma unroll
                    for (int nj = 0; nj < 8; nj++) {
                        int kp2 = kbase + nj * 8 + (l & 3) * 2;
                        if (kp2     > r0)     s_[mi][nj][0] = -1e30f;
                        if (kp2 + 1 > r0)     s_[mi][nj][1] = -1e30f;
                        if (kp2     > r0 + 8) s_[mi][nj][2] = -1e30f;
                        if (kp2 + 1 > r0 + 8) s_[mi][nj][3] = -1e30f;
                    }
                }
            }

            // ---- online softmax (exp2 domain, ex2.approx) ----
            float mx[4] = {-1e30f, -1e30f, -1e30f, -1e30f};
            #pragma unroll
            for (int mi = 0; mi < 2; mi++)
                #pragma unroll
                for (int nj = 0; nj < 8; nj++) {
                    mx[2 * mi]     = fmaxf(mx[2 * mi],     fmaxf(s_[mi][nj][0], s_[mi][nj][1]));
                    mx[2 * mi + 1] = fmaxf(mx[2 * mi + 1], fmaxf(s_[mi][nj][2], s_[mi][nj][3]));
                }
            #pragma unroll
            for (int r = 0; r < 4; r++) {
                mx[r] = fmaxf(mx[r], __shfl_xor_sync(0xffffffffu, mx[r], 1));
                mx[r] = fmaxf(mx[r], __shfl_xor_sync(0xffffffffu, mx[r], 2));
            }
            float nm[4];
            bool changed = false;
            #pragma unroll
            for (int r = 0; r < 4; r++) {
                nm[r] = fmaxf(rm[r], mx[r]);
                changed |= (nm[r] != rm[r]);
            }
            if (__any_sync(0xffffffffu, changed)) {
                float al[4];
                #pragma unroll
                for (int r = 0; r < 4; r++) {
                    al[r] = ex2(rm[r] - nm[r]);
                    lp[r] *= al[r];
                    rm[r] = nm[r];
                }
                #pragma unroll
                for (int mi = 0; mi < 2; mi++)
                    #pragma unroll
                    for (int dj = 0; dj < 16; dj++) {
                        o[mi][dj][0] *= al[2 * mi];     o[mi][dj][1] *= al[2 * mi];
                        o[mi][dj][2] *= al[2 * mi + 1]; o[mi][dj][3] *= al[2 * mi + 1];
                    }
            }

            #pragma unroll
            for (int mi = 0; mi < 2; mi++) {
                float ps0 = 0.f, ps1 = 0.f;
                #pragma unroll
                for (int nj = 0; nj < 8; nj++) {
                    s_[mi][nj][0] = ex2(s_[mi][nj][0] - rm[2 * mi]);
                    s_[mi][nj][1] = ex2(s_[mi][nj][1] - rm[2 * mi]);
                    s_[mi][nj][2] = ex2(s_[mi][nj][2] - rm[2 * mi + 1]);
                    s_[mi][nj][3] = ex2(s_[mi][nj][3] - rm[2 * mi + 1]);
                    ps0 += s_[mi][nj][0] + s_[mi][nj][1];
                    ps1 += s_[mi][nj][2] + s_[mi][nj][3];
                }
                lp[2 * mi]     += ps0;
                lp[2 * mi + 1] += ps1;
            }

            // ---- O += P V (V frags shared across both sub-tiles) ----
            #pragma unroll
            for (int kks = 0; kks < 4; kks++) {
                uint32_t ap[2][4];
                #pragma unroll
                for (int mi = 0; mi < 2; mi++) {
                    const float* p0 = s_[mi][2 * kks];
                    const float* p1 = s_[mi][2 * kks + 1];
                    ap[mi][0] = h2_as_u32(__floats2half2_rn(p0[0], p0[1]));
                    ap[mi][1] = h2_as_u32(__floats2half2_rn(p0[2], p0[3]));
                    ap[mi][2] = h2_as_u32(__floats2half2_rn(p1[0], p1[1]));
                    ap[mi][3] = h2_as_u32(__floats2half2_rn(p1[2], p1[3]));
                }
                uint32_t rvb = (uint32_t)((kks * 16) * AQROWB) + laV;
                #pragma unroll
                for (int dj2 = 0; dj2 < 8; dj2++) {
                    uint32_t coff = dj2 * 32;
                    uint32_t tv[4];
                    ldsm_x4_t(tv, sVH + rvb + coff);
                    #pragma unroll
                    for (int mi = 0; mi < 2; mi++) {
                        mma_f16(o[mi][2 * dj2],     ap[mi], tv);
                        mma_f16(o[mi][2 * dj2 + 1], ap[mi], tv + 2);
                    }
                }
            }
        }

        // ---- finalize this qtile ----
        #pragma unroll
        for (int r = 0; r < 4; r++) {
            lp[r] += __shfl_xor_sync(0xffffffffu, lp[r], 1);
            lp[r] += __shfl_xor_sync(0xffffffffu, lp[r], 2);
        }
        float inv[4] = {1.0f / lp[0], 1.0f / lp[1], 1.0f / lp[2], 1.0f / lp[3]};

        const int colb = h * HDIM + (l & 3) * 2;
        #pragma unroll
        for (int mi = 0; mi < 2; mi++) {
            size_t row0 = (size_t)(b * SEQ + qbase + wid * 32 + mi * 16 + (l >> 2));
            #pragma unroll
            for (int dj = 0; dj < 16; dj++) {
                int col = colb + dj * 8;
                *(__half2*)(Yh + row0 * DMODEL + col) =
                    __floats2half2_rn(o[mi][dj][0] * inv[2 * mi], o[mi][dj][1] * inv[2 * mi]);
                *(__half2*)(Yh + (row0 + 8) * DMODEL + col) =
                    __floats2half2_rn(o[mi][dj][2] * inv[2 * mi + 1], o[mi][dj][3] * inv[2 * mi + 1]);
            }
        }
    }
}

// ---------------------------------------------------------------------------
extern "C" void kernel_launch(void* const* d_in, const int* in_sizes, int n_in,
                              void* d_out, int out_size)
{
    (void)in_sizes; (void)n_in; (void)out_size;
    const float* x     = (const float*)d_in[0];
    const float* Wq    = (const float*)d_in[1];
    const float* Wkv   = (const float*)d_in[2];
    const float* Wproj = (const float*)d_in[3];
    float* out = (float*)d_out;

    __half *xh, *wh, *wph, *qkvh, *yh;
    cudaGetSymbolAddress((void**)&xh,   g_xh);
    cudaGetSymbolAddress((void**)&wh,   g_wh);
    cudaGetSymbolAddress((void**)&wph,  g_wph);
    cudaGetSymbolAddress((void**)&qkvh, g_qkvh);
    cudaGetSymbolAddress((void**)&yh,   g_yh);

    cudaFuncSetAttribute(gemm_mma<true>,  cudaFuncAttributeMaxDynamicSharedMemorySize, G_SMEM);
    cudaFuncSetAttribute(gemm_mma<false>, cudaFuncAttributeMaxDynamicSharedMemorySize, G_SMEM);
    cudaFuncSetAttribute(attn_mma, cudaFuncAttributeMaxDynamicSharedMemorySize, A_SMEM);

    // 0) all fp32->fp16 conversions in one launch
    cvt_all<<<(CVT_TOTAL + 1023) / 1024, 256>>>(x, Wq, Wkv, Wproj, xh, wh, wph);

    // 1) fused QKV = x [Wq;Wkv]^T  -> fp16 [4096, 3072]
    gemm_mma<true><<<dim3(QKVW / 128, MTOT / 128), 256, G_SMEM>>>(xh, wh, qkvh,
                                                                  MTOT, QKVW, DMODEL);

    // 2) in-place vectorized RoPE on q heads + k heads (scale folded into k)
    rope16<<<(ROPE_TASKS + 255) / 256, 256>>>(qkvh);

    // 3) attention -> yh (fp16), 256-row qtile pairs, grid (4, 32)
    attn_mma<<<dim3(SEQ / 512, BATCH * NHEAD), 256, A_SMEM>>>(qkvh, yh);

    // 4) out = y Wproj^T (fp32)
    gemm_mma<false><<<dim3(DMODEL / 128, MTOT / 128), 256, G_SMEM>>>(yh, wph, out,
                                                                     MTOT, DMODEL, DMODEL);
}